// round 1
// baseline (speedup 1.0000x reference)
#include <cuda_runtime.h>
#include <cuda_bf16.h>
#include <mma.h>
#include <cstdint>

using namespace nvcuda;

#define NTOK 8192
#define HDIM 1024
#define FDIM 4096
#define NEXP 8
#define CAP  1280
#define BUCKET 8192

#define BM 128
#define BN 128
#define BK 32
#define LDA 36
#define LDB 132

// ---------------- device scratch (no allocation allowed) ----------------
__device__ float g_h1[(size_t)NEXP * CAP * FDIM];     // 168 MB
__device__ float g_accum[(size_t)NTOK * HDIM];        // 32 MB
__device__ unsigned long long g_bucket[NEXP * BUCKET];// 512 KB
__device__ int   g_cnt[NEXP];
__device__ int   g_tok[NEXP * CAP];
__device__ float g_gate[NEXP * CAP];
__device__ int   g_kept[NEXP];

// ---------------- init: accum = hidden (residual), zero counts ----------------
__global__ void init_kernel(const float* __restrict__ hidden) {
    size_t i = (size_t)blockIdx.x * blockDim.x + threadIdx.x;
    const float4* src = (const float4*)hidden;
    float4* dst = (float4*)g_accum;
    size_t n4 = (size_t)NTOK * HDIM / 4;
    if (i < n4) dst[i] = src[i];
    if (blockIdx.x == 0 && threadIdx.x < NEXP) g_cnt[threadIdx.x] = 0;
}

// ---------------- router: warp per token ----------------
__global__ void router_kernel(const float* __restrict__ x,
                              const float* __restrict__ Wr,
                              const float* __restrict__ br) {
    int gw = (blockIdx.x * blockDim.x + threadIdx.x) >> 5;
    int lane = threadIdx.x & 31;
    if (gw >= NTOK) return;
    const float* xr = x + (size_t)gw * HDIM;
    float acc[NEXP];
#pragma unroll
    for (int e = 0; e < NEXP; e++) acc[e] = 0.f;
    for (int k = lane; k < HDIM; k += 32) {
        float xv = xr[k];
        const float* wk = Wr + k * NEXP;
#pragma unroll
        for (int e = 0; e < NEXP; e++) acc[e] += xv * wk[e];
    }
#pragma unroll
    for (int o = 16; o; o >>= 1)
#pragma unroll
        for (int e = 0; e < NEXP; e++) acc[e] += __shfl_xor_sync(0xFFFFFFFFu, acc[e], o);
    if (lane == 0) {
#pragma unroll
        for (int e = 0; e < NEXP; e++) acc[e] += br[e];
        // top-2 with lowest-index tie-break (match jax.lax.top_k)
        int i0 = 0;
#pragma unroll
        for (int e = 1; e < NEXP; e++) if (acc[e] > acc[i0]) i0 = e;
        int i1 = -1;
#pragma unroll
        for (int e = 0; e < NEXP; e++) {
            if (e == i0) continue;
            if (i1 < 0 || acc[e] > acc[i1]) i1 = e;
        }
        float v0 = acc[i0], v1 = acc[i1];
        float e1 = __expf(v1 - v0);               // e0 = 1
        float inv = 1.f / (1.f + e1);
        float w0 = inv;
        float w1 = e1 * inv;
        unsigned f0 = (unsigned)(gw * 2 + 0);
        unsigned f1 = (unsigned)(gw * 2 + 1);
        int p0 = atomicAdd(&g_cnt[i0], 1);
        g_bucket[i0 * BUCKET + p0] =
            ((unsigned long long)__float_as_uint(w0) << 32) | (0xFFFFFFFFu - f0);
        int p1 = atomicAdd(&g_cnt[i1], 1);
        g_bucket[i1 * BUCKET + p1] =
            ((unsigned long long)__float_as_uint(w1) << 32) | (0xFFFFFFFFu - f1);
    }
}

// ---------------- per-expert capacity selection: bitonic sort 8192 keys ----------------
__global__ void select_kernel() {
    extern __shared__ unsigned long long keys[]; // BUCKET entries = 64 KB
    int e = blockIdx.x;
    int cnt = g_cnt[e];
    for (int i = threadIdx.x; i < BUCKET; i += blockDim.x)
        keys[i] = (i < cnt) ? g_bucket[e * BUCKET + i] : 0ULL;
    __syncthreads();
    for (int k = 2; k <= BUCKET; k <<= 1) {
        for (int j = k >> 1; j > 0; j >>= 1) {
            for (int i = threadIdx.x; i < BUCKET; i += blockDim.x) {
                int ixj = i ^ j;
                if (ixj > i) {
                    bool desc = ((i & k) == 0);
                    unsigned long long a = keys[i], b2 = keys[ixj];
                    bool sw = desc ? (a < b2) : (a > b2);
                    if (sw) { keys[i] = b2; keys[ixj] = a; }
                }
            }
            __syncthreads();
        }
    }
    int kept = min(cnt, CAP);
    if (threadIdx.x == 0) g_kept[e] = kept;
    for (int i = threadIdx.x; i < CAP; i += blockDim.x) {
        if (i < kept) {
            unsigned long long kk = keys[i];
            unsigned flat = 0xFFFFFFFFu - (unsigned)(kk & 0xFFFFFFFFu);
            g_tok[e * CAP + i] = (int)(flat >> 1);
            g_gate[e * CAP + i] = __uint_as_float((unsigned)(kk >> 32));
        } else {
            g_tok[e * CAP + i] = -1;
            g_gate[e * CAP + i] = 0.f;
        }
    }
}

// ---------------- GEMM1: h1 = gelu(x[tok] @ W1[e] + b1[e]) ----------------
__global__ __launch_bounds__(256) void gemm1_kernel(const float* __restrict__ x,
                                                    const float* __restrict__ W1,
                                                    const float* __restrict__ b1) {
    int e = blockIdx.z;
    int kept = g_kept[e];
    int m0 = blockIdx.y * BM;
    if (m0 >= kept) return;
    int n0 = blockIdx.x * BN;

    __shared__ float sA[BM * LDA];
    __shared__ float sB[BK * LDB];
    __shared__ float stage[8 * 256];
    __shared__ int   sTok[BM];

    int tid = threadIdx.x;
    int warpId = tid >> 5, lane = tid & 31;
    int wm = warpId & 3, wn = warpId >> 2;

    wmma::fragment<wmma::accumulator, 16, 16, 8, float> acc[2][4];
#pragma unroll
    for (int i = 0; i < 2; i++)
#pragma unroll
        for (int j = 0; j < 4; j++) wmma::fill_fragment(acc[i][j], 0.f);

    for (int r = tid; r < BM; r += 256) {
        int m = m0 + r;
        sTok[r] = (m < kept) ? g_tok[e * CAP + m] : -1;
    }
    __syncthreads();

    const float* Wp = W1 + (size_t)e * HDIM * FDIM;

    for (int kt = 0; kt < HDIM; kt += BK) {
#pragma unroll
        for (int i = 0; i < 4; i++) {
            int idx = tid + 256 * i;       // 0..1023
            int r = idx >> 3, c = (idx & 7) << 2;
            int t = sTok[r];
            float4 v = make_float4(0.f, 0.f, 0.f, 0.f);
            if (t >= 0) v = *(const float4*)(x + (size_t)t * HDIM + kt + c);
            float* d = &sA[r * LDA + c];
            d[0] = wmma::__float_to_tf32(v.x);
            d[1] = wmma::__float_to_tf32(v.y);
            d[2] = wmma::__float_to_tf32(v.z);
            d[3] = wmma::__float_to_tf32(v.w);
        }
#pragma unroll
        for (int i = 0; i < 4; i++) {
            int idx = tid + 256 * i;
            int r = idx >> 5, c = (idx & 31) << 2;
            float4 v = *(const float4*)(Wp + (size_t)(kt + r) * FDIM + n0 + c);
            float* d = &sB[r * LDB + c];
            d[0] = wmma::__float_to_tf32(v.x);
            d[1] = wmma::__float_to_tf32(v.y);
            d[2] = wmma::__float_to_tf32(v.z);
            d[3] = wmma::__float_to_tf32(v.w);
        }
        __syncthreads();
#pragma unroll
        for (int ks = 0; ks < BK; ks += 8) {
            wmma::fragment<wmma::matrix_a, 16, 16, 8, wmma::precision::tf32, wmma::row_major> af[2];
#pragma unroll
            for (int i = 0; i < 2; i++)
                wmma::load_matrix_sync(af[i], &sA[(wm * 32 + i * 16) * LDA + ks], LDA);
            wmma::fragment<wmma::matrix_b, 16, 16, 8, wmma::precision::tf32, wmma::row_major> bf[4];
#pragma unroll
            for (int j = 0; j < 4; j++)
                wmma::load_matrix_sync(bf[j], &sB[ks * LDB + wn * 64 + j * 16], LDB);
#pragma unroll
            for (int i = 0; i < 2; i++)
#pragma unroll
                for (int j = 0; j < 4; j++)
                    wmma::mma_sync(acc[i][j], af[i], bf[j], acc[i][j]);
        }
        __syncthreads();
    }

    float* st = &stage[warpId * 256];
#pragma unroll
    for (int i = 0; i < 2; i++)
#pragma unroll
        for (int j = 0; j < 4; j++) {
            wmma::store_matrix_sync(st, acc[i][j], 16, wmma::mem_row_major);
            __syncwarp();
            int gm0 = m0 + wm * 32 + i * 16;
            int gn0 = n0 + wn * 64 + j * 16;
            for (int t2 = lane; t2 < 256; t2 += 32) {
                int rr = t2 >> 4, cc = t2 & 15;
                int m = gm0 + rr;
                if (m < kept) {
                    int n = gn0 + cc;
                    float v = st[t2] + b1[e * FDIM + n];
                    v = 0.5f * v * (1.f + erff(v * 0.70710678118654752f));
                    g_h1[((size_t)e * CAP + m) * FDIM + n] = v;
                }
            }
            __syncwarp();
        }
}

// ---------------- GEMM2: accum[tok] += gate * (h1 @ W2[e] + b2[e]) ----------------
__global__ __launch_bounds__(256) void gemm2_kernel(const float* __restrict__ W2,
                                                    const float* __restrict__ b2) {
    int e = blockIdx.z;
    int kept = g_kept[e];
    int m0 = blockIdx.y * BM;
    if (m0 >= kept) return;
    int n0 = blockIdx.x * BN;

    __shared__ float sA[BM * LDA];
    __shared__ float sB[BK * LDB];
    __shared__ float stage[8 * 256];
    __shared__ int   sTok[BM];
    __shared__ float sGate[BM];

    int tid = threadIdx.x;
    int warpId = tid >> 5, lane = tid & 31;
    int wm = warpId & 3, wn = warpId >> 2;

    wmma::fragment<wmma::accumulator, 16, 16, 8, float> acc[2][4];
#pragma unroll
    for (int i = 0; i < 2; i++)
#pragma unroll
        for (int j = 0; j < 4; j++) wmma::fill_fragment(acc[i][j], 0.f);

    for (int r = tid; r < BM; r += 256) {
        int m = m0 + r;
        if (m < kept) {
            sTok[r] = g_tok[e * CAP + m];
            sGate[r] = g_gate[e * CAP + m];
        } else {
            sTok[r] = -1;
            sGate[r] = 0.f;
        }
    }
    __syncthreads();

    const float* Ap = g_h1 + (size_t)e * CAP * FDIM;
    const float* Wp = W2 + (size_t)e * FDIM * HDIM;

    for (int kt = 0; kt < FDIM; kt += BK) {
#pragma unroll
        for (int i = 0; i < 4; i++) {
            int idx = tid + 256 * i;
            int r = idx >> 3, c = (idx & 7) << 2;
            float4 v = make_float4(0.f, 0.f, 0.f, 0.f);
            if (sTok[r] >= 0) v = *(const float4*)(Ap + (size_t)(m0 + r) * FDIM + kt + c);
            float* d = &sA[r * LDA + c];
            d[0] = wmma::__float_to_tf32(v.x);
            d[1] = wmma::__float_to_tf32(v.y);
            d[2] = wmma::__float_to_tf32(v.z);
            d[3] = wmma::__float_to_tf32(v.w);
        }
#pragma unroll
        for (int i = 0; i < 4; i++) {
            int idx = tid + 256 * i;
            int r = idx >> 5, c = (idx & 31) << 2;
            float4 v = *(const float4*)(Wp + (size_t)(kt + r) * HDIM + n0 + c);
            float* d = &sB[r * LDB + c];
            d[0] = wmma::__float_to_tf32(v.x);
            d[1] = wmma::__float_to_tf32(v.y);
            d[2] = wmma::__float_to_tf32(v.z);
            d[3] = wmma::__float_to_tf32(v.w);
        }
        __syncthreads();
#pragma unroll
        for (int ks = 0; ks < BK; ks += 8) {
            wmma::fragment<wmma::matrix_a, 16, 16, 8, wmma::precision::tf32, wmma::row_major> af[2];
#pragma unroll
            for (int i = 0; i < 2; i++)
                wmma::load_matrix_sync(af[i], &sA[(wm * 32 + i * 16) * LDA + ks], LDA);
            wmma::fragment<wmma::matrix_b, 16, 16, 8, wmma::precision::tf32, wmma::row_major> bf[4];
#pragma unroll
            for (int j = 0; j < 4; j++)
                wmma::load_matrix_sync(bf[j], &sB[ks * LDB + wn * 64 + j * 16], LDB);
#pragma unroll
            for (int i = 0; i < 2; i++)
#pragma unroll
                for (int j = 0; j < 4; j++)
                    wmma::mma_sync(acc[i][j], af[i], bf[j], acc[i][j]);
        }
        __syncthreads();
    }

    float* st = &stage[warpId * 256];
#pragma unroll
    for (int i = 0; i < 2; i++)
#pragma unroll
        for (int j = 0; j < 4; j++) {
            wmma::store_matrix_sync(st, acc[i][j], 16, wmma::mem_row_major);
            __syncwarp();
            int lm0 = wm * 32 + i * 16;           // local row within block tile
            int gn0 = n0 + wn * 64 + j * 16;
            for (int t2 = lane; t2 < 256; t2 += 32) {
                int rr = t2 >> 4, cc = t2 & 15;
                int lr = lm0 + rr;
                int tok = sTok[lr];
                if (tok >= 0) {
                    int n = gn0 + cc;
                    float v = (st[t2] + b2[e * HDIM + n]) * sGate[lr];
                    atomicAdd(&g_accum[(size_t)tok * HDIM + n], v);
                }
            }
            __syncwarp();
        }
}

// ---------------- LayerNorm over accum -> out ----------------
__global__ void ln_kernel(const float* __restrict__ gamma,
                          const float* __restrict__ beta,
                          float* __restrict__ out) {
    int row = blockIdx.x, tid = threadIdx.x;
    const float4* a = (const float4*)(g_accum + (size_t)row * HDIM);
    float4 v = a[tid];
    float s = v.x + v.y + v.z + v.w;
    float q = v.x * v.x + v.y * v.y + v.z * v.z + v.w * v.w;
#pragma unroll
    for (int o = 16; o; o >>= 1) {
        s += __shfl_xor_sync(0xFFFFFFFFu, s, o);
        q += __shfl_xor_sync(0xFFFFFFFFu, q, o);
    }
    __shared__ float ss[8], sq[8];
    if ((tid & 31) == 0) { ss[tid >> 5] = s; sq[tid >> 5] = q; }
    __syncthreads();
    if (tid < 32) {
        s = (tid < 8) ? ss[tid] : 0.f;
        q = (tid < 8) ? sq[tid] : 0.f;
#pragma unroll
        for (int o = 4; o; o >>= 1) {
            s += __shfl_xor_sync(0xFFFFFFFFu, s, o);
            q += __shfl_xor_sync(0xFFFFFFFFu, q, o);
        }
        if (tid == 0) { ss[0] = s; sq[0] = q; }
    }
    __syncthreads();
    float mu = ss[0] * (1.f / HDIM);
    float var = sq[0] * (1.f / HDIM) - mu * mu;
    float rs = rsqrtf(var + 1e-5f);
    float4 gv = ((const float4*)gamma)[tid];
    float4 bv = ((const float4*)beta)[tid];
    float4 o4;
    o4.x = (v.x - mu) * rs * gv.x + bv.x;
    o4.y = (v.y - mu) * rs * gv.y + bv.y;
    o4.z = (v.z - mu) * rs * gv.z + bv.z;
    o4.w = (v.w - mu) * rs * gv.w + bv.w;
    ((float4*)(out + (size_t)row * HDIM))[tid] = o4;
}

// ---------------- launch ----------------
extern "C" void kernel_launch(void* const* d_in, const int* in_sizes, int n_in,
                              void* d_out, int out_size) {
    const float* hidden = (const float*)d_in[0];
    const float* Wr     = (const float*)d_in[1];
    const float* br     = (const float*)d_in[2];
    const float* W1     = (const float*)d_in[3];
    const float* b1     = (const float*)d_in[4];
    const float* W2     = (const float*)d_in[5];
    const float* b2     = (const float*)d_in[6];
    const float* gamma  = (const float*)d_in[7];
    const float* beta   = (const float*)d_in[8];
    float* out = (float*)d_out;

    cudaFuncSetAttribute(select_kernel, cudaFuncAttributeMaxDynamicSharedMemorySize,
                         BUCKET * sizeof(unsigned long long));

    size_t n4 = (size_t)NTOK * HDIM / 4;
    init_kernel<<<(unsigned)((n4 + 511) / 512), 512>>>(hidden);
    router_kernel<<<NTOK / 8, 256>>>(hidden, Wr, br);
    select_kernel<<<NEXP, 1024, BUCKET * sizeof(unsigned long long)>>>();
    dim3 g1(FDIM / BN, (CAP + BM - 1) / BM, NEXP);
    gemm1_kernel<<<g1, 256>>>(hidden, W1, b1);
    dim3 g2(HDIM / BN, (CAP + BM - 1) / BM, NEXP);
    gemm2_kernel<<<g2, 256>>>(W2, b2);
    ln_kernel<<<NTOK, 256>>>(gamma, beta, out);
}

// round 3
// speedup vs baseline: 3.6114x; 3.6114x over previous
#include <cuda_runtime.h>
#include <cuda_fp16.h>
#include <mma.h>
#include <cstdint>
#include <math.h>

using namespace nvcuda;

#define NTOK 8192
#define HDIM 1024
#define FDIM 4096
#define NEXP 8
#define CAP  1280
#define BUCKET 8192

#define BM 128
#define BN 128
#define BK 32
#define LDA 40        // BK + 8 halves pad
#define LDB 136       // BN + 8 halves pad
#define NSTG 3
#define A_ST (BM * LDA)   // halves per A stage
#define B_ST (BK * LDB)   // halves per B stage
#define SMEM_NEED (NSTG * (A_ST + B_ST) * 2 + 8 * 256 * 4)

// ---------------- device scratch (no allocation allowed) ----------------
__device__ __half g_h1[(size_t)NEXP * CAP * FDIM];      // 84 MB fp16
__device__ __half g_xe[(size_t)NEXP * CAP * HDIM];      // 20 MB fp16 gathered A
__device__ __half g_w1h[(size_t)NEXP * HDIM * FDIM];    // 64 MB fp16 [E][K][N]
__device__ __half g_w2h[(size_t)NEXP * FDIM * HDIM];    // 64 MB fp16 [E][K][N]
__device__ float  g_accum[(size_t)NTOK * HDIM];         // 32 MB
__device__ unsigned long long g_bucket[NEXP * BUCKET];
__device__ int    g_cnt[NEXP];
__device__ int    g_tok[NEXP * CAP];
__device__ float  g_gate[NEXP * CAP];
__device__ int    g_kept[NEXP];

// ---------------- helpers ----------------
__device__ __forceinline__ uint32_t smem_u32(const void* p) {
    uint32_t a;
    asm("{ .reg .u64 t; cvta.to.shared.u64 t, %1; cvt.u32.u64 %0, t; }" : "=r"(a) : "l"(p));
    return a;
}
__device__ __forceinline__ void cp16(uint32_t s, const void* g) {
    asm volatile("cp.async.cg.shared.global [%0], [%1], 16;" :: "r"(s), "l"(g));
}
#define CP_COMMIT() asm volatile("cp.async.commit_group;" ::: "memory")
template <int N>
__device__ __forceinline__ void cp_wait() {
    asm volatile("cp.async.wait_group %0;" :: "n"(N) : "memory");
}

// ---------------- init: accum = hidden (residual), zero counts ----------------
__global__ void init_kernel(const float* __restrict__ hidden) {
    size_t i = (size_t)blockIdx.x * blockDim.x + threadIdx.x;
    const float4* src = (const float4*)hidden;
    float4* dst = (float4*)g_accum;
    size_t n4 = (size_t)NTOK * HDIM / 4;
    if (i < n4) dst[i] = src[i];
    if (blockIdx.x == 0 && threadIdx.x < NEXP) g_cnt[threadIdx.x] = 0;
}

// ---------------- fp32 -> fp16 conversion ----------------
__global__ void f2h_kernel(const float* __restrict__ s, __half* __restrict__ d, size_t n4) {
    size_t i = (size_t)blockIdx.x * blockDim.x + threadIdx.x;
    if (i < n4) {
        float4 v = ((const float4*)s)[i];
        __half2* dd = (__half2*)d;
        dd[2 * i + 0] = __floats2half2_rn(v.x, v.y);
        dd[2 * i + 1] = __floats2half2_rn(v.z, v.w);
    }
}

// ---------------- router: warp per token ----------------
__global__ void router_kernel(const float* __restrict__ x,
                              const float* __restrict__ Wr,
                              const float* __restrict__ br) {
    int gw = (blockIdx.x * blockDim.x + threadIdx.x) >> 5;
    int lane = threadIdx.x & 31;
    if (gw >= NTOK) return;
    const float* xr = x + (size_t)gw * HDIM;
    float acc[NEXP];
#pragma unroll
    for (int e = 0; e < NEXP; e++) acc[e] = 0.f;
    for (int k = lane; k < HDIM; k += 32) {
        float xv = xr[k];
        const float* wk = Wr + k * NEXP;
#pragma unroll
        for (int e = 0; e < NEXP; e++) acc[e] += xv * wk[e];
    }
#pragma unroll
    for (int o = 16; o; o >>= 1)
#pragma unroll
        for (int e = 0; e < NEXP; e++) acc[e] += __shfl_xor_sync(0xFFFFFFFFu, acc[e], o);
    if (lane == 0) {
#pragma unroll
        for (int e = 0; e < NEXP; e++) acc[e] += br[e];
        int i0 = 0;
#pragma unroll
        for (int e = 1; e < NEXP; e++) if (acc[e] > acc[i0]) i0 = e;
        int i1 = -1;
#pragma unroll
        for (int e = 0; e < NEXP; e++) {
            if (e == i0) continue;
            if (i1 < 0 || acc[e] > acc[i1]) i1 = e;
        }
        float v0 = acc[i0], v1 = acc[i1];
        float e1 = __expf(v1 - v0);
        float inv = 1.f / (1.f + e1);
        float w0 = inv, w1 = e1 * inv;
        unsigned f0 = (unsigned)(gw * 2 + 0);
        unsigned f1 = (unsigned)(gw * 2 + 1);
        int p0 = atomicAdd(&g_cnt[i0], 1);
        g_bucket[i0 * BUCKET + p0] =
            ((unsigned long long)__float_as_uint(w0) << 32) | (0xFFFFFFFFu - f0);
        int p1 = atomicAdd(&g_cnt[i1], 1);
        g_bucket[i1 * BUCKET + p1] =
            ((unsigned long long)__float_as_uint(w1) << 32) | (0xFFFFFFFFu - f1);
    }
}

// ---------------- per-expert capacity selection: bitonic sort ----------------
__global__ void select_kernel() {
    extern __shared__ unsigned long long keys[];
    int e = blockIdx.x;
    int cnt = g_cnt[e];
    for (int i = threadIdx.x; i < BUCKET; i += blockDim.x)
        keys[i] = (i < cnt) ? g_bucket[e * BUCKET + i] : 0ULL;
    __syncthreads();
    for (int k = 2; k <= BUCKET; k <<= 1) {
        for (int j = k >> 1; j > 0; j >>= 1) {
            for (int i = threadIdx.x; i < BUCKET; i += blockDim.x) {
                int ixj = i ^ j;
                if (ixj > i) {
                    bool desc = ((i & k) == 0);
                    unsigned long long a = keys[i], b2 = keys[ixj];
                    bool swp = desc ? (a < b2) : (a > b2);
                    if (swp) { keys[i] = b2; keys[ixj] = a; }
                }
            }
            __syncthreads();
        }
    }
    int kept = min(cnt, CAP);
    if (threadIdx.x == 0) g_kept[e] = kept;
    for (int i = threadIdx.x; i < CAP; i += blockDim.x) {
        if (i < kept) {
            unsigned long long kk = keys[i];
            unsigned flat = 0xFFFFFFFFu - (unsigned)(kk & 0xFFFFFFFFu);
            g_tok[e * CAP + i] = (int)(flat >> 1);
            g_gate[e * CAP + i] = __uint_as_float((unsigned)(kk >> 32));
        } else {
            g_tok[e * CAP + i] = -1;
            g_gate[e * CAP + i] = 0.f;
        }
    }
}

// ---------------- gather: pack x[tok] -> fp16 dense A; zero padding ----------------
__global__ void gather_kernel(const float* __restrict__ x) {
    int slot = blockIdx.x;
    int tok = g_tok[slot];
    __half2* dst = (__half2*)(g_xe + (size_t)slot * HDIM);
    int t = threadIdx.x;                  // 256 threads, 4 elems each
    if (tok >= 0) {
        float4 v = ((const float4*)(x + (size_t)tok * HDIM))[t];
        dst[2 * t + 0] = __floats2half2_rn(v.x, v.y);
        dst[2 * t + 1] = __floats2half2_rn(v.z, v.w);
    } else {
        dst[2 * t + 0] = __half2half2(__float2half(0.f));
        dst[2 * t + 1] = __half2half2(__float2half(0.f));
    }
}

// ---------------- stage loader: A [BM x BK], B [BK x BN] fp16 ----------------
__device__ __forceinline__ void load_stage(int tid, uint32_t sAb, uint32_t sBb, int s,
                                           const __half* Ab, const __half* Bb,
                                           int astr, int bstr, int kt) {
#pragma unroll
    for (int i = 0; i < 2; i++) {          // A: 128 rows x 4 chunks(16B)
        int c = tid + 256 * i;
        int r = c >> 2, ch = c & 3;
        cp16(sAb + ((uint32_t)(s * A_ST + r * LDA + ch * 8)) * 2,
             Ab + (size_t)r * astr + kt * BK + ch * 8);
    }
#pragma unroll
    for (int i = 0; i < 2; i++) {          // B: 32 rows x 16 chunks(16B)
        int c = tid + 256 * i;
        int r = c >> 4, ch = c & 15;
        cp16(sBb + ((uint32_t)(s * B_ST + r * LDB + ch * 8)) * 2,
             Bb + (size_t)(kt * BK + r) * bstr + ch * 8);
    }
}

// ---------------- fp16 wmma GEMM (G1: x@W1+GELU->h1 ; !G1: h1@W2 gated scatter) ----------------
template <int KT, int AST, int BST, bool G1>
__global__ void __launch_bounds__(256) gemm_h(const float* __restrict__ bias) {
    int e = blockIdx.z;
    int kept = g_kept[e];
    int m0 = blockIdx.y * BM;
    if (m0 >= kept) return;
    int n0 = blockIdx.x * BN;

    extern __shared__ __half smem[];
    __half* sA = smem;
    __half* sB = smem + NSTG * A_ST;
    float* stg = (float*)(sB + NSTG * B_ST);
    uint32_t sAb = smem_u32(sA), sBb = smem_u32(sB);

    int tid = threadIdx.x;
    int warpId = tid >> 5, lane = tid & 31;
    int wm = warpId & 3, wn = warpId >> 2;

    const __half* Ab;
    const __half* Bb;
    if (G1) {
        Ab = g_xe + (size_t)(e * CAP + m0) * AST;
        Bb = g_w1h + (size_t)e * HDIM * FDIM + n0;
    } else {
        Ab = g_h1 + (size_t)(e * CAP + m0) * AST;
        Bb = g_w2h + (size_t)e * FDIM * HDIM + n0;
    }

    wmma::fragment<wmma::accumulator, 16, 16, 16, float> acc[2][4];
#pragma unroll
    for (int i = 0; i < 2; i++)
#pragma unroll
        for (int j = 0; j < 4; j++) wmma::fill_fragment(acc[i][j], 0.f);

    // prologue: fill NSTG-1 stages
#pragma unroll
    for (int s = 0; s < NSTG - 1; s++) {
        load_stage(tid, sAb, sBb, s, Ab, Bb, AST, BST, s);
        CP_COMMIT();
    }

    for (int kt = 0; kt < KT; kt++) {
        cp_wait<NSTG - 2>();
        __syncthreads();
        if (kt + NSTG - 1 < KT)
            load_stage(tid, sAb, sBb, (kt + NSTG - 1) % NSTG, Ab, Bb, AST, BST, kt + NSTG - 1);
        CP_COMMIT();

        int st = kt % NSTG;
#pragma unroll
        for (int ks = 0; ks < BK; ks += 16) {
            wmma::fragment<wmma::matrix_a, 16, 16, 16, __half, wmma::row_major> af[2];
#pragma unroll
            for (int i = 0; i < 2; i++)
                wmma::load_matrix_sync(af[i], &sA[st * A_ST + (wm * 32 + i * 16) * LDA + ks], LDA);
            wmma::fragment<wmma::matrix_b, 16, 16, 16, __half, wmma::row_major> bf[4];
#pragma unroll
            for (int j = 0; j < 4; j++)
                wmma::load_matrix_sync(bf[j], &sB[st * B_ST + ks * LDB + wn * 64 + j * 16], LDB);
#pragma unroll
            for (int i = 0; i < 2; i++)
#pragma unroll
                for (int j = 0; j < 4; j++)
                    wmma::mma_sync(acc[i][j], af[i], bf[j], acc[i][j]);
        }
    }
    __syncthreads();

    // epilogue
    float* st = &stg[warpId * 256];
#pragma unroll
    for (int i = 0; i < 2; i++)
#pragma unroll
        for (int j = 0; j < 4; j++) {
            wmma::store_matrix_sync(st, acc[i][j], 16, wmma::mem_row_major);
            __syncwarp();
            int lm0 = wm * 32 + i * 16;
            int gn0 = n0 + wn * 64 + j * 16;
            if (G1) {
                for (int t2 = lane; t2 < 256; t2 += 32) {
                    int rr = t2 >> 4, cc = t2 & 15;
                    int m = m0 + lm0 + rr;
                    if (m < kept) {
                        int n = gn0 + cc;
                        float v = st[t2] + bias[e * FDIM + n];
                        v = 0.5f * v * (1.f + erff(v * 0.70710678118654752f));
                        g_h1[((size_t)e * CAP + m) * FDIM + n] = __float2half_rn(v);
                    }
                }
            } else {
                for (int t2 = lane; t2 < 256; t2 += 32) {
                    int rr = t2 >> 4, cc = t2 & 15;
                    int m = m0 + lm0 + rr;
                    int tok = (m < kept) ? g_tok[e * CAP + m] : -1;
                    if (tok >= 0) {
                        int n = gn0 + cc;
                        float gate = g_gate[e * CAP + m];
                        float v = (st[t2] + bias[e * HDIM + n]) * gate;
                        atomicAdd(&g_accum[(size_t)tok * HDIM + n], v);
                    }
                }
            }
            __syncwarp();
        }
}

// ---------------- LayerNorm over accum -> out ----------------
__global__ void ln_kernel(const float* __restrict__ gamma,
                          const float* __restrict__ beta,
                          float* __restrict__ out) {
    int row = blockIdx.x, tid = threadIdx.x;
    const float4* a = (const float4*)(g_accum + (size_t)row * HDIM);
    float4 v = a[tid];
    float s = v.x + v.y + v.z + v.w;
    float q = v.x * v.x + v.y * v.y + v.z * v.z + v.w * v.w;
#pragma unroll
    for (int o = 16; o; o >>= 1) {
        s += __shfl_xor_sync(0xFFFFFFFFu, s, o);
        q += __shfl_xor_sync(0xFFFFFFFFu, q, o);
    }
    __shared__ float ss[8], sq[8];
    if ((tid & 31) == 0) { ss[tid >> 5] = s; sq[tid >> 5] = q; }
    __syncthreads();
    if (tid < 32) {
        s = (tid < 8) ? ss[tid] : 0.f;
        q = (tid < 8) ? sq[tid] : 0.f;
#pragma unroll
        for (int o = 4; o; o >>= 1) {
            s += __shfl_xor_sync(0xFFFFFFFFu, s, o);
            q += __shfl_xor_sync(0xFFFFFFFFu, q, o);
        }
        if (tid == 0) { ss[0] = s; sq[0] = q; }
    }
    __syncthreads();
    float mu = ss[0] * (1.f / HDIM);
    float var = sq[0] * (1.f / HDIM) - mu * mu;
    float rs = rsqrtf(var + 1e-5f);
    float4 gv = ((const float4*)gamma)[tid];
    float4 bv = ((const float4*)beta)[tid];
    float4 o4;
    o4.x = (v.x - mu) * rs * gv.x + bv.x;
    o4.y = (v.y - mu) * rs * gv.y + bv.y;
    o4.z = (v.z - mu) * rs * gv.z + bv.z;
    o4.w = (v.w - mu) * rs * gv.w + bv.w;
    ((float4*)(out + (size_t)row * HDIM))[tid] = o4;
}

// ---------------- launch ----------------
extern "C" void kernel_launch(void* const* d_in, const int* in_sizes, int n_in,
                              void* d_out, int out_size) {
    const float* hidden = (const float*)d_in[0];
    const float* Wr     = (const float*)d_in[1];
    const float* br     = (const float*)d_in[2];
    const float* W1     = (const float*)d_in[3];
    const float* b1     = (const float*)d_in[4];
    const float* W2     = (const float*)d_in[5];
    const float* b2     = (const float*)d_in[6];
    const float* gamma  = (const float*)d_in[7];
    const float* beta   = (const float*)d_in[8];
    float* out = (float*)d_out;

    cudaFuncSetAttribute(select_kernel, cudaFuncAttributeMaxDynamicSharedMemorySize,
                         BUCKET * sizeof(unsigned long long));
    cudaFuncSetAttribute(gemm_h<HDIM / BK, HDIM, FDIM, true>,
                         cudaFuncAttributeMaxDynamicSharedMemorySize, SMEM_NEED);
    cudaFuncSetAttribute(gemm_h<FDIM / BK, FDIM, HDIM, false>,
                         cudaFuncAttributeMaxDynamicSharedMemorySize, SMEM_NEED);

    __half* w1h; cudaGetSymbolAddress((void**)&w1h, g_w1h);
    __half* w2h; cudaGetSymbolAddress((void**)&w2h, g_w2h);

    size_t n4 = (size_t)NTOK * HDIM / 4;
    init_kernel<<<(unsigned)((n4 + 511) / 512), 512>>>(hidden);
    size_t w4 = (size_t)NEXP * HDIM * FDIM / 4;
    f2h_kernel<<<(unsigned)((w4 + 511) / 512), 512>>>(W1, w1h, w4);
    f2h_kernel<<<(unsigned)((w4 + 511) / 512), 512>>>(W2, w2h, w4);
    router_kernel<<<NTOK / 8, 256>>>(hidden, Wr, br);
    select_kernel<<<NEXP, 1024, BUCKET * sizeof(unsigned long long)>>>();
    gather_kernel<<<NEXP * CAP, 256>>>(hidden);
    gemm_h<HDIM / BK, HDIM, FDIM, true>
        <<<dim3(FDIM / BN, CAP / BM, NEXP), 256, SMEM_NEED>>>(b1);
    gemm_h<FDIM / BK, FDIM, HDIM, false>
        <<<dim3(HDIM / BN, CAP / BM, NEXP), 256, SMEM_NEED>>>(b2);
    ln_kernel<<<NTOK, 256>>>(gamma, beta, out);
}